// round 10
// baseline (speedup 1.0000x reference)
#include <cuda_runtime.h>
#include <cstdint>
#include <cstddef>

#define T_STEPS  100
#define BATCH    256
#define IN_DIM   1024
#define HID      2048
#define OUT_DIM  10
#define DECAY    0.9f
#define THRESH   1.0f
#define CH       64          // k-elements per pipeline chunk

// ---------------- device scratch (static, no allocations) ----------------
__device__ float g_X[(size_t)T_STEPS * BATCH * IN_DIM];   // transposed input: [T][B][IN]
__device__ float g_s1[2 * BATCH * HID];
__device__ float g_s2[2 * BATCH * HID];
__device__ float g_v1[BATCH * HID];
__device__ float g_v2[BATCH * HID];
__device__ float g_vout[BATCH * OUT_DIM];
__device__ float g_acc[BATCH * OUT_DIM];

// ---------------- helpers ----------------
__device__ __forceinline__ uint32_t smem_u32(const void* p) {
    uint32_t a;
    asm("{ .reg .u64 t; cvta.to.shared.u64 t, %1; cvt.u32.u64 %0, t; }" : "=r"(a) : "l"(p));
    return a;
}

// ---------------- transpose input_bins [B,IN_DIM,T] -> X [T, B*IN_DIM] ----------------
__global__ void transpose_kernel(const float* __restrict__ in)
{
    __shared__ float tile[32][33];
    int t0  = blockIdx.x * 32;
    int bi0 = blockIdx.y * 32;
    int tx = threadIdx.x, ty = threadIdx.y;

    #pragma unroll
    for (int r = ty; r < 32; r += 8) {
        int bi = bi0 + r, t = t0 + tx;
        tile[r][tx] = (t < T_STEPS) ? in[(size_t)bi * T_STEPS + t] : 0.0f;
    }
    __syncthreads();
    #pragma unroll
    for (int r = ty; r < 32; r += 8) {
        int t = t0 + r, bi = bi0 + tx;
        if (t < T_STEPS)
            g_X[(size_t)t * (BATCH * IN_DIM) + bi] = tile[tx][r];
    }
}

__global__ void zero_state_kernel()
{
    int i = blockIdx.x * 256 + threadIdx.x;
    if (i < BATCH * HID) { g_v1[i] = 0.0f; g_v2[i] = 0.0f; }
    if (i < BATCH * OUT_DIM) { g_vout[i] = 0.0f; g_acc[i] = 0.0f; }
}

// ---------------- fp32 GEMM tile (64x64) + fused LIF, packed f32x2 FMA ----------------
// Per output: strict ascending-k single-accumulator fma.rn chain (lane-wise identical
// to the validated scalar-FFMA R7/R8 kernels -> bitwise identical results).
__device__ __forceinline__ void gemm_tile(
    const float* __restrict__ A, const float* __restrict__ B,
    float* __restrict__ v, float* __restrict__ s,
    int N, int K, int bx, int by, float* pool)
{
    float (*As)[68] = (float (*)[68])pool;            // [k][m], padded
    float (*Bs)[68] = (float (*)[68])(pool + CH * 68);// [k][n], padded

    int tid = threadIdx.x;
    int m0 = by * 64;
    int n0 = bx * 64;
    int r = (tid >> 4) << 2;       // 0..60 step 4 (m offset)
    int c = (tid & 15) << 2;       // 0..60 step 4 (n offset)

    uint32_t asBase = smem_u32(&As[0][0]);

    // packed accumulators: accP[mp][j] holds rows (r+2mp, r+2mp+1) for col c+j
    // lo = even row, hi = odd row; ull(0) == {+0.0f, +0.0f}
    unsigned long long accP[2][4] = {{0ull,0ull,0ull,0ull},{0ull,0ull,0ull,0ull}};

    const int nch = K / CH;
    float4 aReg[4], bReg[4];

    // prefetch chunk 0 into registers
    #pragma unroll
    for (int e = 0; e < 4; e++) {
        int idx = tid + e * 256;
        int m  = idx >> 4, k4 = (idx & 15) << 2;
        aReg[e] = *(const float4*)&A[(size_t)(m0 + m) * K + k4];
        bReg[e] = *(const float4*)&B[(size_t)(idx >> 4) * N + n0 + ((idx & 15) << 2)];
    }
    // stage chunk 0 (A transposed)
    #pragma unroll
    for (int e = 0; e < 4; e++) {
        int idx = tid + e * 256;
        int m  = idx >> 4, k4 = (idx & 15) << 2;
        As[k4 + 0][m] = aReg[e].x;
        As[k4 + 1][m] = aReg[e].y;
        As[k4 + 2][m] = aReg[e].z;
        As[k4 + 3][m] = aReg[e].w;
        *(float4*)&Bs[idx >> 4][(idx & 15) << 2] = bReg[e];
    }
    __syncthreads();

    for (int ch = 0; ch < nch; ch++) {
        // issue next-chunk global loads (latency hidden under compute)
        if (ch + 1 < nch) {
            int k0 = (ch + 1) * CH;
            #pragma unroll
            for (int e = 0; e < 4; e++) {
                int idx = tid + e * 256;
                int m  = idx >> 4, k4 = (idx & 15) << 2;
                aReg[e] = *(const float4*)&A[(size_t)(m0 + m) * K + k0 + k4];
                bReg[e] = *(const float4*)&B[(size_t)(k0 + (idx >> 4)) * N + n0 + ((idx & 15) << 2)];
            }
        }

        // compute: ascending k, one packed fma per k per output-pair
        #pragma unroll 16
        for (int k = 0; k < CH; k++) {
            unsigned long long aP0, aP1;
            asm("ld.shared.v2.u64 {%0,%1}, [%2];"
                : "=l"(aP0), "=l"(aP1)
                : "r"(asBase + (uint32_t)(k * 68 + r) * 4));
            float4 b4 = *(const float4*)&Bs[k][c];
            unsigned long long bd0, bd1, bd2, bd3;
            asm("mov.b64 %0, {%1,%1};" : "=l"(bd0) : "f"(b4.x));
            asm("mov.b64 %0, {%1,%1};" : "=l"(bd1) : "f"(b4.y));
            asm("mov.b64 %0, {%1,%1};" : "=l"(bd2) : "f"(b4.z));
            asm("mov.b64 %0, {%1,%1};" : "=l"(bd3) : "f"(b4.w));
            asm("fma.rn.f32x2 %0, %1, %2, %0;" : "+l"(accP[0][0]) : "l"(aP0), "l"(bd0));
            asm("fma.rn.f32x2 %0, %1, %2, %0;" : "+l"(accP[0][1]) : "l"(aP0), "l"(bd1));
            asm("fma.rn.f32x2 %0, %1, %2, %0;" : "+l"(accP[0][2]) : "l"(aP0), "l"(bd2));
            asm("fma.rn.f32x2 %0, %1, %2, %0;" : "+l"(accP[0][3]) : "l"(aP0), "l"(bd3));
            asm("fma.rn.f32x2 %0, %1, %2, %0;" : "+l"(accP[1][0]) : "l"(aP1), "l"(bd0));
            asm("fma.rn.f32x2 %0, %1, %2, %0;" : "+l"(accP[1][1]) : "l"(aP1), "l"(bd1));
            asm("fma.rn.f32x2 %0, %1, %2, %0;" : "+l"(accP[1][2]) : "l"(aP1), "l"(bd2));
            asm("fma.rn.f32x2 %0, %1, %2, %0;" : "+l"(accP[1][3]) : "l"(aP1), "l"(bd3));
        }
        __syncthreads();

        if (ch + 1 < nch) {
            #pragma unroll
            for (int e = 0; e < 4; e++) {
                int idx = tid + e * 256;
                int m  = idx >> 4, k4 = (idx & 15) << 2;
                As[k4 + 0][m] = aReg[e].x;
                As[k4 + 1][m] = aReg[e].y;
                As[k4 + 2][m] = aReg[e].z;
                As[k4 + 3][m] = aReg[e].w;
                *(float4*)&Bs[idx >> 4][(idx & 15) << 2] = bReg[e];
            }
            __syncthreads();
        }
    }

    // unpack accumulators: row r+i gets acc[i>>1] lo/hi halves
    float acc[4][4];
    #pragma unroll
    for (int mp = 0; mp < 2; mp++) {
        #pragma unroll
        for (int j = 0; j < 4; j++) {
            float lo, hi;
            asm("mov.b64 {%0,%1}, %2;" : "=f"(lo), "=f"(hi) : "l"(accP[mp][j]));
            acc[2 * mp][j]     = lo;
            acc[2 * mp + 1][j] = hi;
        }
    }

    // fused LIF epilogue (elementwise; numerics identical to R7/R8)
    #pragma unroll
    for (int i = 0; i < 4; i++) {
        size_t base = (size_t)(m0 + r + i) * N + (n0 + c);
        float4 vv = *(const float4*)&v[base];
        float t0 = vv.x * DECAY + acc[i][0];
        float t1 = vv.y * DECAY + acc[i][1];
        float t2 = vv.z * DECAY + acc[i][2];
        float t3 = vv.w * DECAY + acc[i][3];
        bool p0 = t0 >= THRESH, p1 = t1 >= THRESH, p2 = t2 >= THRESH, p3 = t3 >= THRESH;
        float4 vn, sn;
        vn.x = p0 ? 0.0f : t0; vn.y = p1 ? 0.0f : t1;
        vn.z = p2 ? 0.0f : t2; vn.w = p3 ? 0.0f : t3;
        sn.x = p0 ? 1.0f : 0.0f; sn.y = p1 ? 1.0f : 0.0f;
        sn.z = p2 ? 1.0f : 0.0f; sn.w = p3 ? 1.0f : 0.0f;
        *(float4*)&v[base] = vn;
        *(float4*)&s[base] = sn;
    }
}

// ---------------- fused step: blocks [0,128)=L2(t), [128,256)=L1(t+1), [256,384)=OUT(t-1) ----------------
__global__ __launch_bounds__(256) void fused_step_kernel(
    const float* __restrict__ Xt,
    const float* __restrict__ W_ih,
    const float* __restrict__ W_hh,
    const float* __restrict__ W_ho,
    const float* __restrict__ s1r, float* __restrict__ s1w,
    const float* __restrict__ s2r, float* __restrict__ s2w,
    int doL1, int doL2, int doOUT)
{
    __shared__ float pool[2 * CH * 68];   // 34816 B
    int blk = blockIdx.x;
    int tid = threadIdx.x;

    if (blk < 128) {                       // ---- L2(t)
        if (!doL2) return;
        gemm_tile(s1r, W_hh, g_v2, s2w, HID, HID, blk & 31, blk >> 5, pool);
    } else if (blk < 256) {                // ---- L1(t+1)
        if (!doL1) return;
        int b2 = blk - 128;
        gemm_tile(Xt, W_ih, g_v1, s1w, HID, IN_DIM, b2 & 31, b2 >> 5, pool);
    } else {                               // ---- OUT(t-1)
        if (!doOUT) return;
        int group = tid >> 7;
        int lt    = tid & 127;
        int b     = (blk - 256) * 2 + group;

        float accv[OUT_DIM];
        #pragma unroll
        for (int o = 0; o < OUT_DIM; o++) accv[o] = 0.0f;

        const float* srow = s2r + (size_t)b * HID;
        for (int i = lt; i < HID; i += 128) {
            float sv = srow[i];
            if (sv != 0.0f) {
                #pragma unroll
                for (int o = 0; o < OUT_DIM; o++)
                    accv[o] += W_ho[(size_t)i * OUT_DIM + o];
            }
        }

        float* red = pool;                 // [2][OUT_DIM][128]
        #pragma unroll
        for (int o = 0; o < OUT_DIM; o++) red[(group * OUT_DIM + o) * 128 + lt] = accv[o];
        __syncthreads();

        for (int stride = 64; stride > 0; stride >>= 1) {
            if (lt < stride) {
                #pragma unroll
                for (int o = 0; o < OUT_DIM; o++)
                    red[(group * OUT_DIM + o) * 128 + lt] +=
                        red[(group * OUT_DIM + o) * 128 + lt + stride];
            }
            __syncthreads();
        }

        if (lt < OUT_DIM) {
            float cur = red[(group * OUT_DIM + lt) * 128];
            int idx = b * OUT_DIM + lt;
            float vv = g_vout[idx] * DECAY + cur;
            bool sp = (vv >= THRESH);
            g_vout[idx] = sp ? 0.0f : vv;
            if (sp) g_acc[idx] += 1.0f;
        }
    }
}

__global__ void finalize_kernel(float* __restrict__ out)
{
    int i = blockIdx.x * 256 + threadIdx.x;
    if (i < BATCH * OUT_DIM) out[i] = g_acc[i] * (1.0f / T_STEPS);
}

// ---------------- launch ----------------
extern "C" void kernel_launch(void* const* d_in, const int* in_sizes, int n_in,
                              void* d_out, int out_size)
{
    const float* in_bins = (const float*)d_in[0];   // [256,1024,100]
    const float* W_ih    = (const float*)d_in[1];   // [1024,2048]
    const float* W_hh    = (const float*)d_in[2];   // [1,2048,2048]
    const float* W_ho    = (const float*)d_in[3];   // [2048,10]
    float* out = (float*)d_out;

    float *X, *s1, *s2;
    cudaGetSymbolAddress((void**)&X,  g_X);
    cudaGetSymbolAddress((void**)&s1, g_s1);
    cudaGetSymbolAddress((void**)&s2, g_s2);

    // 1) transpose input
    {
        dim3 grid((T_STEPS + 31) / 32, (BATCH * IN_DIM) / 32);
        transpose_kernel<<<grid, dim3(32, 8)>>>(in_bins);
    }
    // 2) zero persistent state
    zero_state_kernel<<<(BATCH * HID + 255) / 256, 256>>>();

    // 3) software-pipelined time loop: call i runs L1(t=i), L2(t=i-1), OUT(t=i-2)
    for (int i = 0; i <= T_STEPS + 1; i++) {
        int ti = (i < T_STEPS) ? i : (T_STEPS - 1);
        const float* Xt  = X + (size_t)ti * BATCH * IN_DIM;
        float* s1w = s1 + (size_t)(i & 1) * BATCH * HID;
        const float* s1r = s1 + (size_t)((i - 1) & 1) * BATCH * HID;
        float* s2w = s2 + (size_t)((i - 1) & 1) * BATCH * HID;
        const float* s2r = s2 + (size_t)((i - 2) & 1) * BATCH * HID;
        int doL1  = (i < T_STEPS);
        int doL2  = (i >= 1) && (i <= T_STEPS);
        int doOUT = (i >= 2);
        fused_step_kernel<<<384, 256>>>(Xt, W_ih, W_hh, W_ho,
                                        s1r, s1w, s2r, s2w, doL1, doL2, doOUT);
    }

    // 4) finalize
    finalize_kernel<<<(BATCH * OUT_DIM + 255) / 256, 256>>>(out);
}